// round 17
// baseline (speedup 1.0000x reference)
#include <cuda_runtime.h>
#include <cuda_fp16.h>
#include <cstdint>

#define NN 256
#define HH 128
#define RR 8

typedef unsigned long long u64;

// packed f16x2 proj outputs: [2048 rows][64 kpairs] NATURAL order (kpair m = col m)
__device__ uint32_t g_pi_h[2048 * 64];
__device__ uint32_t g_pj_h[2048 * 64];
// factorized exact terms: u = pi@W2, v = pj@W2 (f32)
__device__ float g_u[2048 * 8];
__device__ float g_v[2048 * 8];

// fragment-order position (proj smem only)
#define FPOS(kp) ((((kp) >> 3) << 3) + (((kp) & 3) << 1) + (((kp) >> 2) & 1))

// int8 quantization constants
#define S2V 0.08838834764831845f            // 1/sqrt(128), W2 bound
#define INV_SW (127.0f / S2V)               // W2 -> int units
#define SW (S2V / 127.0f)
#define SH (4.0f / 255.0f)                  // |s| step (offset-binary)
#define SCALE_T (0.5f * SH * SW)            // ½·sh·sw

// ---------------- helpers ----------------
__device__ __forceinline__ uint32_t hadd2(uint32_t a, uint32_t b) {
    uint32_t d; asm("add.rn.f16x2 %0, %1, %2;" : "=r"(d) : "r"(a), "r"(b)); return d;
}
__device__ __forceinline__ uint32_t hfma2(uint32_t a, uint32_t b, uint32_t c) {
    uint32_t d; asm("fma.rn.f16x2 %0, %1, %2, %3;" : "=r"(d) : "r"(a), "r"(b), "r"(c)); return d;
}
__device__ __forceinline__ uint32_t prmt6420(uint32_t a, uint32_t b) {
    uint32_t d; asm("prmt.b32 %0, %1, %2, 0x6420;" : "=r"(d) : "r"(a), "r"(b)); return d;
}
__device__ __forceinline__ uint32_t pack_f16x2(float lo, float hi) {
    uint32_t d; asm("cvt.rn.f16x2.f32 %0, %1, %2;" : "=r"(d) : "f"(hi), "f"(lo)); return d;
}
__device__ __forceinline__ void mma16816(float* d, uint32_t a0, uint32_t a1,
                                         uint32_t a2, uint32_t a3,
                                         uint32_t b0, uint32_t b1) {
    asm("mma.sync.aligned.m16n8k16.row.col.f32.f16.f16.f32 "
        "{%0,%1,%2,%3}, {%4,%5,%6,%7}, {%8,%9}, {%0,%1,%2,%3};"
        : "+f"(d[0]), "+f"(d[1]), "+f"(d[2]), "+f"(d[3])
        : "r"(a0), "r"(a1), "r"(a2), "r"(a3), "r"(b0), "r"(b1));
}
__device__ __forceinline__ void mma_s8(int* d, uint32_t a0, uint32_t a1,
                                       uint32_t a2, uint32_t a3,
                                       uint32_t b0, uint32_t b1) {
    asm("mma.sync.aligned.m16n8k32.row.col.s32.s8.s8.s32 "
        "{%0,%1,%2,%3}, {%4,%5,%6,%7}, {%8,%9}, {%0,%1,%2,%3};"
        : "+r"(d[0]), "+r"(d[1]), "+r"(d[2]), "+r"(d[3])
        : "r"(a0), "r"(a1), "r"(a2), "r"(a3), "r"(b0), "r"(b1));
}
// sigmoid(x + 2*hb) = 0.5 + 0.5*tanh(0.5*x + hb)
__device__ __forceinline__ float sigm(float x, float hb) {
    float t, a = fmaf(0.5f, x, hb);
    asm("tanh.approx.f32 %0, %1;" : "=f"(t) : "f"(a));
    return fmaf(0.5f, t, 0.5f);
}

// -------------------------------------------------------------------------
// Phase A (HMMA): proj = slots[2048,256] @ W1cat[256,256] (+b1 on pj half).
// Unchanged proven body; writes g_pi_h / g_pj_h in natural kpair order.
// -------------------------------------------------------------------------
#define A_STR64 68
#define W_STR 72
#define PROJ_SMEM (32 * A_STR64 * 8 + 128 * W_STR * 4)

__global__ __launch_bounds__(256) void proj_kernel(
    const float* __restrict__ slots,
    const float* __restrict__ W1,
    const float* __restrict__ b1)
{
    extern __shared__ __align__(16) u64 psm[];
    uint32_t* Asw = (uint32_t*)psm;
    uint32_t* Ws  = (uint32_t*)(psm + 32 * A_STR64);

    const int tid = threadIdx.x;
    const int ct = blockIdx.x, rt = blockIdx.y;
    const int row0 = rt * 32;
    const int which = ct >> 1;
    const int hbase = (ct & 1) * 64;

    {
        const float2* sp = (const float2*)(slots + (size_t)row0 * 256);
        #pragma unroll
        for (int it = 0; it < 16; it++) {
            int e = tid + it * 256;
            int r = e >> 7, c2 = e & 127;
            float2 v = sp[r * 128 + c2];
            Asw[r * 136 + FPOS(c2)] = pack_f16x2(v.x, v.y);
        }
    }
    {
        #pragma unroll
        for (int it = 0; it < 16; it++) {
            int e = tid + it * 256;
            int kp = e >> 5, n2 = e & 31;
            const float* wb = W1 + (size_t)(which * 256 + 2 * kp) * HH + hbase + 2 * n2;
            float2 f0 = *(const float2*)wb;
            float2 f1 = *(const float2*)(wb + HH);
            u64 two = ((u64)pack_f16x2(f0.y, f1.y) << 32) | pack_f16x2(f0.x, f1.x);
            *(u64*)(Ws + kp * W_STR + 2 * n2) = two;
        }
    }
    __syncthreads();

    const int w = tid >> 5, lane = tid & 31;
    const int g = lane >> 2, t = lane & 3;
    const int wm = w & 1, wn = w >> 1;

    float ce[2][4] = {{0.f,0.f,0.f,0.f},{0.f,0.f,0.f,0.f}};
    float co[2][4] = {{0.f,0.f,0.f,0.f},{0.f,0.f,0.f,0.f}};
    const uint32_t* Ar0 = Asw + (wm * 16 + g) * 136;
    const uint32_t* Ar8 = Ar0 + 8 * 136;
    const int n0 = wn * 16 + g;

    #pragma unroll
    for (int s = 0; s < 16; s++) {
        u64 av0 = *(const u64*)(Ar0 + 8 * s + 2 * t);
        u64 av8 = *(const u64*)(Ar8 + 8 * s + 2 * t);
        uint32_t a0 = (uint32_t)av0, a2 = (uint32_t)(av0 >> 32);
        uint32_t a1 = (uint32_t)av8, a3 = (uint32_t)(av8 >> 32);
        const uint32_t* B0 = Ws + (8 * s + t) * W_STR;
        const uint32_t* B4 = B0 + 4 * W_STR;
        float* c0 = (s & 1) ? co[0] : ce[0];
        float* c1 = (s & 1) ? co[1] : ce[1];
        mma16816(c0, a0, a1, a2, a3, B0[n0],     B4[n0]);
        mma16816(c1, a0, a1, a2, a3, B0[n0 + 8], B4[n0 + 8]);
    }

    uint32_t* dst = which ? g_pj_h : g_pi_h;
    #pragma unroll
    for (int nt = 0; nt < 2; nt++) {
        float2 bias = make_float2(0.f, 0.f);
        if (which)
            bias = *(const float2*)(b1 + hbase + wn * 16 + nt * 8 + 2 * t);
        float c0 = ce[nt][0] + co[nt][0] + bias.x;
        float c1 = ce[nt][1] + co[nt][1] + bias.y;
        float c2 = ce[nt][2] + co[nt][2] + bias.x;
        float c3 = ce[nt][3] + co[nt][3] + bias.y;
        int cp = (ct & 1) * 32 + wn * 8 + nt * 4 + t;
        int r0 = row0 + wm * 16 + g;
        dst[(size_t)r0 * 64 + cp]       = pack_f16x2(c0, c1);
        dst[(size_t)(r0 + 8) * 64 + cp] = pack_f16x2(c2, c3);
    }
}

// -------------------------------------------------------------------------
// uv kernel: u = pi @ W2, v = pj @ W2 (f32 accum). 32 CTAs x 256 thr,
// warp task = (half u/v, 16-row tile), 8 HMMAs, A frags straight from global.
// -------------------------------------------------------------------------
__global__ __launch_bounds__(256) void uv_kernel(const float* __restrict__ W2)
{
    const int tid = threadIdx.x;
    const int w = tid >> 5, lane = tid & 31;
    const int g = lane >> 2, t = lane & 3;
    const int task = blockIdx.x * 8 + w;     // 0..255
    const int half = task & 1;               // 0 -> u/pi, 1 -> v/pj
    const int rt16 = task >> 1;              // 0..127

    const uint32_t* src = half ? g_pj_h : g_pi_h;
    float* dst = half ? g_v : g_u;

    uint32_t w2f[8][2];
    #pragma unroll
    for (int s = 0; s < 8; s++) {
        int k0 = 16 * s + 2 * t;
        w2f[s][0] = pack_f16x2(W2[k0 * RR + g],       W2[(k0 + 1) * RR + g]);
        w2f[s][1] = pack_f16x2(W2[(k0 + 8) * RR + g], W2[(k0 + 9) * RR + g]);
    }

    const int row0 = rt16 * 16 + g;
    const uint32_t* r0p = src + (size_t)row0 * 64;
    const uint32_t* r8p = r0p + 8 * 64;

    float d[4] = {0.f, 0.f, 0.f, 0.f};
    #pragma unroll
    for (int s = 0; s < 8; s++) {
        uint32_t a0 = r0p[8 * s + t];
        uint32_t a1 = r8p[8 * s + t];
        uint32_t a2 = r0p[8 * s + 4 + t];
        uint32_t a3 = r8p[8 * s + 4 + t];
        mma16816(d, a0, a1, a2, a3, w2f[s][0], w2f[s][1]);
    }
    *(float2*)(dst + (size_t)row0 * 8 + 2 * t)       = make_float2(d[0], d[1]);
    *(float2*)(dst + (size_t)(row0 + 8) * 8 + 2 * t) = make_float2(d[2], d[3]);
}

// -------------------------------------------------------------------------
// Phase B (int8 m16n8k32): grid (jq=4, itile=16, b=8) = 512 CTAs, 256 thr.
// logit = ½(u+v) + ½·sh·sw·(D + 128·csum) + b2;  |s| quantized offset-binary
// via f16 magic 1408 + PRMT. pj/pi staged NATURAL u64 order (stride 36 u64).
// -------------------------------------------------------------------------
__global__ __launch_bounds__(256, 2) void pair_i8_kernel(
    const float* __restrict__ W2,
    const float* __restrict__ b2,
    float* __restrict__ out)
{
    __shared__ __align__(16) u64 pj64[64 * 36];
    __shared__ __align__(16) u64 pi64[16 * 36];
    __shared__ __align__(16) u64 w2i[128];        // [kb*32 + lane] = {b0, b1}
    __shared__ float u_s[16 * 8];
    __shared__ float v_s[64 * 8];
    __shared__ float sb_s[8];                     // SCALE_T * 128 * csum[r]

    const int tid = threadIdx.x;
    const int w = tid >> 5, lane = tid & 31;
    const int g = lane >> 2, t = lane & 3;
    const int wj = w & 3, wi = w >> 2;
    const int jq = blockIdx.x, itile = blockIdx.y, b = blockIdx.z;

    // ---- staging ----
    {
        const u64* src = (const u64*)(g_pj_h + (((size_t)b * NN + jq * 64) << 6));
        #pragma unroll
        for (int it = 0; it < 8; it++) {
            int e = tid + it * 256;
            pj64[(e >> 5) * 36 + (e & 31)] = src[e];
        }
        const u64* si = (const u64*)(g_pi_h + (((size_t)b * NN + itile * 16) << 6));
        #pragma unroll
        for (int it = 0; it < 2; it++) {
            int e = tid + it * 256;
            pi64[(e >> 5) * 36 + (e & 31)] = si[e];
        }
        if (tid < 128)
            u_s[tid] = g_u[(((size_t)b * NN + itile * 16) << 3) + tid];
        #pragma unroll
        for (int it = 0; it < 2; it++) {
            int e = tid + it * 256;
            v_s[e] = g_v[(((size_t)b * NN + jq * 64) << 3) + e];
        }
        // W2 int8 fragments: w2i[kb*32+lane] = {b0: k 32kb+4t.., b1: k 32kb+16+4t..}, n=g
        if (tid < 128) {
            int kb = tid >> 5, ln = tid & 31;
            int gg = ln >> 2, tt = ln & 3;
            uint32_t bq[2];
            #pragma unroll
            for (int hh = 0; hh < 2; hh++) {
                uint32_t p = 0;
                #pragma unroll
                for (int jj = 0; jj < 4; jj++) {
                    int k = 32 * kb + 16 * hh + 4 * tt + jj;
                    int qi = __float2int_rn(W2[k * RR + gg] * INV_SW);
                    qi = max(-127, min(127, qi));
                    p |= ((uint32_t)qi & 255u) << (8 * jj);
                }
                bq[hh] = p;
            }
            w2i[tid] = ((u64)bq[1] << 32) | bq[0];
        }
        if (tid < 8) {
            int s = 0;
            #pragma unroll 8
            for (int k = 0; k < 128; k++) {
                int qi = __float2int_rn(W2[k * RR + tid] * INV_SW);
                s += max(-127, min(127, qi));
            }
            sb_s[tid] = SCALE_T * 128.0f * (float)s;
        }
    }
    const float2 b2v = *(const float2*)(b2 + 2 * t);
    const float hbx = 0.5f * b2v.x, hby = 0.5f * b2v.y;
    const uint32_t INV = pack_f16x2(63.75f, 63.75f);    // 255/4
    const uint32_t MAG = pack_f16x2(1408.0f, 1408.0f);  // 1536 - 128
    const uint32_t ABS2 = 0x7FFF7FFFu;

    __syncthreads();

    // hoist pj + W2 fragments
    u64 pjf[4][4];      // [kb][rowg-A, rowg-B, rowg8-A, rowg8-B]
    u64 w2f[4];
    {
        const u64* r0 = pj64 + (wj * 16 + g) * 36;
        const u64* r8 = r0 + 8 * 36;
        #pragma unroll
        for (int kb = 0; kb < 4; kb++) {
            pjf[kb][0] = r0[8 * kb + t];
            pjf[kb][1] = r0[8 * kb + 4 + t];
            pjf[kb][2] = r8[8 * kb + t];
            pjf[kb][3] = r8[8 * kb + 4 + t];
            w2f[kb] = w2i[kb * 32 + lane];
        }
    }
    const float2 sb = make_float2(sb_s[2 * t], sb_s[2 * t + 1]);
    const float2 vg  = *(const float2*)&v_s[(wj * 16 + g) * 8 + 2 * t];
    const float2 vg8 = *(const float2*)&v_s[(wj * 16 + g + 8) * 8 + 2 * t];

    const size_t obase =
        (((size_t)b * NN + itile * 16 + wi * 8) * NN + jq * 64 + wj * 16) * RR;

    #pragma unroll 1
    for (int ii = 0; ii < 4; ii++) {
        const int il0 = wi * 8 + 2 * ii;
        const u64* pr0 = pi64 + il0 * 36;
        const u64* pr1 = pr0 + 36;
        int d0[4] = {0, 0, 0, 0};
        int d1[4] = {0, 0, 0, 0};
        #pragma unroll
        for (int kb = 0; kb < 4; kb++) {
            u64 piA0 = pr0[8 * kb + t], piB0 = pr0[8 * kb + 4 + t];
            u64 piA1 = pr1[8 * kb + t], piB1 = pr1[8 * kb + 4 + t];
            uint32_t wb0 = (uint32_t)w2f[kb], wb1 = (uint32_t)(w2f[kb] >> 32);

            // q8: s=pi+pj -> |s| -> *63.75 + 1408 -> bytes (offset-binary)
            #define Q8(piv, pjv, dst_) {                                         \
                uint32_t s0 = hadd2((uint32_t)(piv), (uint32_t)(pjv));           \
                uint32_t s1 = hadd2((uint32_t)((piv) >> 32),                     \
                                    (uint32_t)((pjv) >> 32));                    \
                uint32_t y0 = hfma2(s0 & ABS2, INV, MAG);                        \
                uint32_t y1 = hfma2(s1 & ABS2, INV, MAG);                        \
                dst_ = prmt6420(y0, y1); }

            uint32_t a0, a1, a2, a3;
            Q8(piA0, pjf[kb][0], a0); Q8(piA0, pjf[kb][2], a1);
            Q8(piB0, pjf[kb][1], a2); Q8(piB0, pjf[kb][3], a3);
            mma_s8(d0, a0, a1, a2, a3, wb0, wb1);
            Q8(piA1, pjf[kb][0], a0); Q8(piA1, pjf[kb][2], a1);
            Q8(piB1, pjf[kb][1], a2); Q8(piB1, pjf[kb][3], a3);
            mma_s8(d1, a0, a1, a2, a3, wb0, wb1);
            #undef Q8
        }
        const float2 uu0 = *(const float2*)&u_s[il0 * 8 + 2 * t];
        const float2 uu1 = *(const float2*)&u_s[(il0 + 1) * 8 + 2 * t];

        float x00 = 0.5f * (uu0.x + vg.x)  + SCALE_T * (float)d0[0] + sb.x;
        float x01 = 0.5f * (uu0.y + vg.y)  + SCALE_T * (float)d0[1] + sb.y;
        float x02 = 0.5f * (uu0.x + vg8.x) + SCALE_T * (float)d0[2] + sb.x;
        float x03 = 0.5f * (uu0.y + vg8.y) + SCALE_T * (float)d0[3] + sb.y;
        float x10 = 0.5f * (uu1.x + vg.x)  + SCALE_T * (float)d1[0] + sb.x;
        float x11 = 0.5f * (uu1.y + vg.y)  + SCALE_T * (float)d1[1] + sb.y;
        float x12 = 0.5f * (uu1.x + vg8.x) + SCALE_T * (float)d1[2] + sb.x;
        float x13 = 0.5f * (uu1.y + vg8.y) + SCALE_T * (float)d1[3] + sb.y;

        float* op0 = out + obase + (size_t)(2 * ii) * NN * RR + 2 * t;
        float* op1 = op0 + NN * RR;
        *(float2*)(op0 + g * RR)       = make_float2(sigm(x00, hbx), sigm(x01, hby));
        *(float2*)(op0 + (g + 8) * RR) = make_float2(sigm(x02, hbx), sigm(x03, hby));
        *(float2*)(op1 + g * RR)       = make_float2(sigm(x10, hbx), sigm(x11, hby));
        *(float2*)(op1 + (g + 8) * RR) = make_float2(sigm(x12, hbx), sigm(x13, hby));
    }
}

extern "C" void kernel_launch(void* const* d_in, const int* in_sizes, int n_in,
                              void* d_out, int out_size)
{
    const float* slots = (const float*)d_in[0];
    const float* W1    = (const float*)d_in[1];
    const float* b1    = (const float*)d_in[2];
    const float* W2    = (const float*)d_in[3];
    const float* b2    = (const float*)d_in[4];
    float* out = (float*)d_out;

    cudaFuncSetAttribute(proj_kernel,
                         cudaFuncAttributeMaxDynamicSharedMemorySize, PROJ_SMEM);

    proj_kernel<<<dim3(4, 64), 256, PROJ_SMEM>>>(slots, W1, b1);
    uv_kernel<<<32, 256>>>(W2);
    pair_i8_kernel<<<dim3(4, 16, 8), 256>>>(W2, b2, out);
}